// round 15
// baseline (speedup 1.0000x reference)
#include <cuda_runtime.h>
#include <cuda_bf16.h>
#include <cstdint>
#include <math.h>

// Problem constants
#define NB   32
#define TLEN 512
#define DDIM 1024
#define CDIM 120
#define NROWS 96
#define INV_SCALE 0.015625f // 1/64
#define TOTROWS 49152
#define BR_STRIDE 16384     // compact rows per branch (max 32*512)

#define NEG_INF __int_as_float(0xff800000)

// ---------------- scratch (device globals) ----------------------------------
__device__ float g_xsum[NROWS * DDIM];
__device__ float g_nv[NROWS];
__device__ float g_u[NROWS * DDIM];
__device__ float g_ub[NROWS];
__device__ float g_v[NROWS * DDIM];
__device__ float g_attn[3 * BR_STRIDE];   // compacted softmax weights
__device__ int   g_batchof[3 * BR_STRIDE];
__device__ float g_ph[NROWS * DDIM];
__device__ float g_pooled[NROWS * DDIM];
__device__ int   g_rank[NROWS * TLEN];    // local rank within batch, -1 masked
__device__ int   g_V[NROWS];              // valid count per batch-row
__device__ int   g_off[NROWS];            // exclusive offset of batch in branch
__device__ int   g_total[3];              // valid tokens per branch
// tf32 operands (globally compacted per branch; stored as fp32 bit patterns)
__device__ float g_xtf[(size_t)TOTROWS * DDIM];
__device__ float g_wtf[DDIM * DDIM];      // W1 transposed, tf32-rounded

// =================== helpers =================================================
__device__ __forceinline__ void cp16(void* d, const void* s) {
    asm volatile("cp.async.cg.shared.global [%0], [%1], 16;"
                 :: "l"(__cvta_generic_to_shared(d)), "l"(s));
}
__device__ __forceinline__ void cp_commit() {
    asm volatile("cp.async.commit_group;" ::: "memory");
}
__device__ __forceinline__ void cp_wait0() {
    asm volatile("cp.async.wait_group 0;" ::: "memory");
}
__device__ __forceinline__ void mma_tf32(float* d, const uint32_t* a, const uint32_t* b) {
    asm volatile(
        "mma.sync.aligned.m16n8k8.row.col.f32.tf32.tf32.f32 "
        "{%0,%1,%2,%3}, {%4,%5,%6,%7}, {%8,%9}, {%0,%1,%2,%3};"
        : "+f"(d[0]), "+f"(d[1]), "+f"(d[2]), "+f"(d[3])
        : "r"(a[0]), "r"(a[1]), "r"(a[2]), "r"(a[3]), "r"(b[0]), "r"(b[1]));
}
__device__ __forceinline__ void ldm4(uint32_t* r, uint32_t saddr) {
    asm volatile("ldmatrix.sync.aligned.m8n8.x4.shared.b16 {%0,%1,%2,%3}, [%4];"
                 : "=r"(r[0]), "=r"(r[1]), "=r"(r[2]), "=r"(r[3]) : "r"(saddr));
}
__device__ __forceinline__ float f2tf(float f) {
    uint32_t r;
    asm("cvt.rna.tf32.f32 %0, %1;" : "=r"(r) : "f"(f));
    return __uint_as_float(r);
}

// SMEM layout of big kernel: 2 stages x 55296B (M=256 x N=128 x K=32 tf32)
// row stride 144B (36 floats): ldmatrix row-starts hit disjoint bank quads.
#define ROW_B     144
#define APLANE    36864            // A plane: 256 rows x 144B
#define STAGE_B   55296            // + B plane: 128 rows x 144B
#define OFF_ATT   110592  // 256 floats
#define OFF_BAT   111616  // 256 ints
#define OFF_B1    112640  // 128 floats
#define OFF_COL   113152  // 128 floats
#define SMEM_REQ  113664

// ---------------- K0: zero scratch + conv W1 -> tf32 transposed -------------
__global__ void combo_kernel(const float* __restrict__ W1,
                             float* __restrict__ wtf,
                             float* __restrict__ ph, float* __restrict__ xsum,
                             float* __restrict__ u, float* __restrict__ v,
                             float* __restrict__ pooled, float* __restrict__ ub,
                             float* __restrict__ attn) {
    int bx = blockIdx.x;
    if (bx < 384) {
        int i = bx * 256 + threadIdx.x;   // covers 98304
        ph[i] = 0.f; xsum[i] = 0.f; u[i] = 0.f; v[i] = 0.f; pooled[i] = 0.f;
        if (i < NROWS) ub[i] = 0.f;
        if (i < 3 * BR_STRIDE) attn[i] = 0.f;
    } else {
        __shared__ float tile[32][33];
        int b = bx - 384;
        int n0 = (b & 31) * 32, k0 = (b >> 5) * 32;
        int tx = threadIdx.x & 31, ty = threadIdx.x >> 5;
        for (int r = ty; r < 32; r += 8)
            tile[r][tx] = W1[(size_t)(k0 + r) * DDIM + n0 + tx];
        __syncthreads();
        for (int r = ty; r < 32; r += 8) {
            size_t o = (size_t)(n0 + r) * DDIM + k0 + tx;
            wtf[o] = f2tf(tile[tx][r]);   // = W1[k0+tx][n0+r]
        }
    }
}

// ---------------- K0b: mask scan via ballot/popcount -------------------------
__global__ void mask_scan_kernel(const int* __restrict__ m0, const int* __restrict__ m1,
                                 const int* __restrict__ m2,
                                 int* __restrict__ rank, int* __restrict__ V,
                                 float* __restrict__ nv) {
    int b = blockIdx.x, br = blockIdx.y;
    const int* M = ((br == 0) ? m0 : (br == 1) ? m1 : m2) + (size_t)b * TLEN;
    int row = br * NB + b;
    int tid = threadIdx.x;  // 512
    int lane = tid & 31, w = tid >> 5;
    __shared__ int wbase[16];
    int valid = (M[tid] == 0) ? 1 : 0;
    unsigned bal = __ballot_sync(0xffffffffu, valid);
    int pre = __popc(bal & ((1u << lane) - 1u));
    if (lane == 31) wbase[w] = pre + valid;
    __syncthreads();
    if (w == 0) {
        int v16 = (lane < 16) ? wbase[lane] : 0;
        int s = v16;
#pragma unroll
        for (int o = 1; o < 16; o <<= 1) {
            int t = __shfl_up_sync(0xffffffffu, s, o);
            if (lane >= o) s += t;
        }
        if (lane < 16) wbase[lane] = s - v16;   // exclusive
        if (lane == 15) { V[row] = s; nv[row] = (float)s; }
    }
    __syncthreads();
    rank[row * TLEN + tid] = valid ? (wbase[w] + pre) : -1;
}

// ---------------- K0c: offsets (warp scan) + pad fill of batchof -------------
__global__ void offsets_kernel(const int* __restrict__ V, int* __restrict__ off,
                               int* __restrict__ total, int* __restrict__ batchof) {
    int tid = threadIdx.x;   // 96
    if (tid >= 96) return;
    int br = tid >> 5, lane = tid & 31;
    int v = V[br * 32 + lane];
    int s = v;
#pragma unroll
    for (int o = 1; o < 32; o <<= 1) {
        int t = __shfl_up_sync(0xffffffffu, s, o);
        if (lane >= o) s += t;
    }
    off[br * 32 + lane] = s - v;
    int tot = __shfl_sync(0xffffffffu, s, 31);
    if (lane == 31) total[br] = tot;
    int up = (tot + 255) & ~255;      // pad to M=256 tile granularity
    for (int i = tot + lane; i < up; i += 32)
        batchof[br * BR_STRIDE + i] = NB - 1;
}

// ---------------- fused: valid x -> compacted tf32 plane + masked sum -------
// grid (16, 32, 3): 32-token chunks.
__global__ void convsum_kernel(const float* __restrict__ x0, const float* __restrict__ x1,
                               const float* __restrict__ x2,
                               const int* __restrict__ rank,
                               const int* __restrict__ off,
                               float* __restrict__ xtf,
                               float* __restrict__ xsum, int* __restrict__ batchof) {
    int ch = blockIdx.x, b = blockIdx.y, br = blockIdx.z;
    const float* X = (br == 0) ? x0 : (br == 1) ? x1 : x2;
    int row = br * NB + b;
    __shared__ int smr[32];
    __shared__ int soff;
    int tid = threadIdx.x;
    if (tid < 32) smr[tid] = rank[row * TLEN + ch * 32 + tid];
    if (tid == 0) soff = off[row];
    __syncthreads();
    size_t cbase = (size_t)br * BR_STRIDE + soff;
    if (tid < 32 && smr[tid] >= 0) batchof[cbase + smr[tid]] = b;

    const float* xp = X + ((size_t)b * TLEN + ch * 32) * DDIM + tid * 4;
    float ax = 0.f, ay = 0.f, az = 0.f, aw = 0.f;
#pragma unroll 1
    for (int t = 0; t < 32; t += 2) {
        int rk0 = smr[t], rk1 = smr[t + 1];
        float4 v0, v1;
        if (rk0 >= 0) v0 = *(const float4*)(xp + (size_t)t * DDIM);
        if (rk1 >= 0) v1 = *(const float4*)(xp + (size_t)(t + 1) * DDIM);
        if (rk0 >= 0) {
            float4 o4;
            o4.x = f2tf(v0.x); o4.y = f2tf(v0.y);
            o4.z = f2tf(v0.z); o4.w = f2tf(v0.w);
            *(float4*)(xtf + (cbase + rk0) * DDIM + tid * 4) = o4;
            ax += v0.x; ay += v0.y; az += v0.z; aw += v0.w;
        }
        if (rk1 >= 0) {
            float4 o4;
            o4.x = f2tf(v1.x); o4.y = f2tf(v1.y);
            o4.z = f2tf(v1.z); o4.w = f2tf(v1.w);
            *(float4*)(xtf + (cbase + rk1) * DDIM + tid * 4) = o4;
            ax += v1.x; ay += v1.y; az += v1.z; aw += v1.w;
        }
    }
    float* xr = xsum + (size_t)row * DDIM + tid * 4;
    atomicAdd(xr + 0, ax);
    atomicAdd(xr + 1, ay);
    atomicAdd(xr + 2, az);
    atomicAdd(xr + 3, aw);
}

// ---------------- small GEMM, K-split x8: (96 x 1024) @ (1024 x 1024) -------
template <int MODE>
__global__ void gemm96_kernel(const float* __restrict__ A, const float* __restrict__ B,
                              float* __restrict__ C, const float* __restrict__ bias,
                              const float* __restrict__ nv, float* __restrict__ ub) {
    const int BK = 32;
    __shared__ float As[32][BK + 1];
    __shared__ float Bs[BK][64 + 1];
    int m0 = blockIdx.y * 32;
    int n0 = blockIdx.x * 64;
    int ks = blockIdx.z * 128;
    int tid = threadIdx.x;
    int tx = tid & 15, ty = tid >> 4;
    int lane = tid & 31;

    float acc[2][4] = {{0.f, 0.f, 0.f, 0.f}, {0.f, 0.f, 0.f, 0.f}};

    for (int k0 = ks; k0 < ks + 128; k0 += BK) {
#pragma unroll
        for (int i = 0; i < 4; i++) {
            int l = tid + i * 256;
            int r = l >> 5, k = l & 31;
            As[r][k] = A[(size_t)(m0 + r) * DDIM + k0 + k];
        }
        if (MODE == 1) {
#pragma unroll
            for (int i = 0; i < 8; i++) {
                int l = tid + i * 256;
                int kk = l & 31, n = l >> 5;
                Bs[kk][n] = B[(size_t)(n0 + n) * DDIM + k0 + kk];
            }
        } else {
#pragma unroll
            for (int i = 0; i < 8; i++) {
                int l = tid + i * 256;
                int kk = l >> 6, n = l & 63;
                Bs[kk][n] = B[(size_t)(k0 + kk) * DDIM + n0 + n];
            }
        }
        __syncthreads();
#pragma unroll
        for (int kk = 0; kk < BK; kk++) {
            float a0 = As[ty * 2 + 0][kk];
            float a1 = As[ty * 2 + 1][kk];
#pragma unroll
            for (int j = 0; j < 4; j++) {
                float bv = Bs[kk][tx * 4 + j];
                acc[0][j] += a0 * bv;
                acc[1][j] += a1 * bv;
            }
        }
        __syncthreads();
    }

    float vv[2][4];
#pragma unroll
    for (int i = 0; i < 2; i++) {
        int r = m0 + ty * 2 + i;
#pragma unroll
        for (int j = 0; j < 4; j++) {
            int c = n0 + tx * 4 + j;
            float v = acc[i][j];
            if (MODE == 0 && blockIdx.z == 0) v += nv[r] * bias[c];
            if (MODE == 2 && blockIdx.z == 0) v += bias[c];
            vv[i][j] = v;
            atomicAdd(&C[(size_t)r * DDIM + c], v);
        }
    }
    if (MODE == 0) {
        float u0 = 0.f, u1 = 0.f;
#pragma unroll
        for (int j = 0; j < 4; j++) {
            float ba = bias[n0 + tx * 4 + j];
            u0 += vv[0][j] * ba;
            u1 += vv[1][j] * ba;
        }
#pragma unroll
        for (int o = 8; o > 0; o >>= 1) {
            u0 += __shfl_xor_sync(0xffffffffu, u0, o);
            u1 += __shfl_xor_sync(0xffffffffu, u1, o);
        }
        if ((lane & 15) == 0) {
            atomicAdd(&ub[m0 + ty * 2 + 0], u0);
            atomicAdd(&ub[m0 + ty * 2 + 1], u1);
        }
    }
}

// ---------------- K3+K4 fused: scores over compact tf32 plane + softmax -----
// grid (NB, 3), 512 threads; warp = one token, strided by 16.
__global__ void s_softmax_kernel(const float* __restrict__ xtf,
                                 const int* __restrict__ off, const int* __restrict__ V,
                                 const float* __restrict__ v, const float* __restrict__ ub,
                                 float* __restrict__ attn) {
    int b = blockIdx.x, br = blockIdx.y;
    int row = br * NB + b;
    int base = off[row];
    int Vr = V[row];
    int tid = threadIdx.x;
    int w = tid >> 5, lane = tid & 31;
    __shared__ float sbuf[TLEN];
    __shared__ float red[512];
    float ubr = ub[row];
    const float* vr = v + (size_t)row * DDIM;

    for (int t = w; t < Vr; t += 16) {
        size_t cr = (size_t)br * BR_STRIDE + base + t;
        const float* xr = xtf + cr * DDIM;
        float acc = 0.f;
#pragma unroll
        for (int i = 0; i < 8; i++) {
            int d = lane * 4 + i * 128;
            float4 xv = *(const float4*)&xr[d];
            float4 vv = *(const float4*)&vr[d];
            acc += xv.x * vv.x + xv.y * vv.y + xv.z * vv.z + xv.w * vv.w;
        }
#pragma unroll
        for (int o = 16; o > 0; o >>= 1) acc += __shfl_xor_sync(0xffffffffu, acc, o);
        if (lane == 0) sbuf[t] = (acc + ubr) * INV_SCALE;
    }
    __syncthreads();

    float v0 = (tid < Vr) ? sbuf[tid] : NEG_INF;
    red[tid] = v0;
    __syncthreads();
    for (int st = 256; st > 0; st >>= 1) {
        if (tid < st) red[tid] = fmaxf(red[tid], red[tid + st]);
        __syncthreads();
    }
    float mx = red[0];
    __syncthreads();
    float e0 = (tid < Vr) ? expf(v0 - mx) : 0.f;
    red[tid] = e0;
    __syncthreads();
    for (int st = 256; st > 0; st >>= 1) {
        if (tid < st) red[tid] += red[tid + st];
        __syncthreads();
    }
    float inv = 1.0f / red[0];
    if (tid < Vr) attn[(size_t)br * BR_STRIDE + base + tid] = e0 * inv;
}

// ---------------- K5: single-pass tf32 mma GEMM, M=256 x N=128 --------------
// grid (8, 192): bx = N-block; branch = by>>6, tile = by&63 (256 rows each).
// 512 threads, 4x4 warps, 64x32 warp tile; single-sync pipeline; occ 1.
__global__ __launch_bounds__(512, 1) void big_mma_kernel(
    const float* __restrict__ xtf, const float* __restrict__ wtf,
    const float* __restrict__ b1, const float* __restrict__ attn,
    const int* __restrict__ batchof, const int* __restrict__ total,
    float* __restrict__ ph) {
    extern __shared__ __align__(16) char smc[];
    float* att_s = (float*)(smc + OFF_ATT);
    int*   bat_s = (int*)(smc + OFF_BAT);
    float* b1s   = (float*)(smc + OFF_B1);
    float* cols  = (float*)(smc + OFF_COL);
    uint32_t sbase = (uint32_t)__cvta_generic_to_shared(smc);

    int by = blockIdx.y;
    int branch = by >> 6, tile = by & 63;
    if (tile * 256 >= total[branch]) return;

    int tid = threadIdx.x;
    int wid = tid >> 5, lane = tid & 31;
    int wm = wid >> 2, wn = wid & 3;
    int g = lane >> 2, tg = lane & 3;
    int n0 = blockIdx.x * 128;
    size_t rowbase = (size_t)branch * BR_STRIDE + tile * 256;

    auto load_stage = [&](int st) {
        char* buf = smc + (st & 1) * STAGE_B;
        int k0 = st * 32;
#pragma unroll
        for (int c = tid; c < 2048; c += 512) {
            int r = c >> 3, j = c & 7;
            cp16(buf + r * ROW_B + j * 16, xtf + (rowbase + r) * DDIM + k0 + j * 4);
        }
#pragma unroll
        for (int c = tid; c < 1024; c += 512) {
            int r = c >> 3, j = c & 7;
            cp16(buf + APLANE + r * ROW_B + j * 16,
                 wtf + (size_t)(n0 + r) * DDIM + k0 + j * 4);
        }
    };

    load_stage(0); cp_commit();

    if (tid < 256) {
        att_s[tid] = attn[rowbase + tid];
        bat_s[tid] = batchof[rowbase + tid];
        if (tid < 128) b1s[tid] = b1[n0 + tid];
    }

    float acc[4][4][4];
#pragma unroll
    for (int mi = 0; mi < 4; mi++)
#pragma unroll
        for (int ni = 0; ni < 4; ni++)
#pragma unroll
            for (int j = 0; j < 4; j++) acc[mi][ni][j] = 0.f;

    uint32_t a_l = (uint32_t)((wm * 64 + (lane & 15)) * ROW_B + (lane >> 4) * 16);
    uint32_t b_l = (uint32_t)((wn * 32 + (lane & 7) + ((lane >> 4) << 3)) * ROW_B +
                              ((lane >> 3) & 1) * 16);

    for (int st = 0; st < 32; ++st) {
        cp_wait0();
        __syncthreads();
        if (st + 1 < 32) { load_stage(st + 1); cp_commit(); }
        uint32_t buf = sbase + (uint32_t)(st & 1) * STAGE_B;
#pragma unroll
        for (int kb = 0; kb < 4; ++kb) {
            uint32_t aoff = buf + a_l + (uint32_t)kb * 32u;
            uint32_t boff = buf + APLANE + b_l + (uint32_t)kb * 32u;
            uint32_t a[4][4], b[2][4];
#pragma unroll
            for (int mi = 0; mi < 4; mi++) ldm4(a[mi], aoff + mi * (16 * ROW_B));
#pragma unroll
            for (int p = 0; p < 2; p++) ldm4(b[p], boff + p * (16 * ROW_B));
#pragma unroll
            for (int mi = 0; mi < 4; mi++)
#pragma unroll
                for (int ni = 0; ni < 4; ni++)
                    mma_tf32(acc[mi][ni], a[mi], &b[ni >> 1][(ni & 1) * 2]);
        }
    }

    // ---- epilogue: relu precompute, then per-segment weighted reduce --------
#pragma unroll
    for (int mi = 0; mi < 4; mi++)
#pragma unroll
        for (int ni = 0; ni < 4; ni++) {
            int c0 = wn * 32 + ni * 8 + tg * 2;
            float bv0 = b1s[c0], bv1 = b1s[c0 + 1];
            acc[mi][ni][0] = fmaxf(acc[mi][ni][0] + bv0, 0.f);
            acc[mi][ni][1] = fmaxf(acc[mi][ni][1] + bv1, 0.f);
            acc[mi][ni][2] = fmaxf(acc[mi][ni][2] + bv0, 0.f);
            acc[mi][ni][3] = fmaxf(acc[mi][ni][3] + bv1, 0.f);
        }
    int batch0 = bat_s[0];
    int nseg = bat_s[255] - batch0 + 1;
    for (int sg = 0; sg < nseg; ++sg) {
        int bsel = batch0 + sg;
        if (tid < 128) cols[tid] = 0.f;
        __syncthreads();
#pragma unroll
        for (int mi = 0; mi < 4; mi++) {
            int rA = wm * 64 + mi * 16 + g;
            float wA = (bat_s[rA] == bsel) ? att_s[rA] : 0.f;
            float wB = (bat_s[rA + 8] == bsel) ? att_s[rA + 8] : 0.f;
#pragma unroll
            for (int ni = 0; ni < 4; ni++) {
                int c0 = wn * 32 + ni * 8 + tg * 2;
                float v0 = acc[mi][ni][0] * wA + acc[mi][ni][2] * wB;
                float v1 = acc[mi][ni][1] * wA + acc[mi][ni][3] * wB;
#pragma unroll
                for (int o = 4; o <= 16; o <<= 1) {
                    v0 += __shfl_xor_sync(0xffffffffu, v0, o);
                    v1 += __shfl_xor_sync(0xffffffffu, v1, o);
                }
                if (g == 0) {
                    atomicAdd(&cols[c0], v0);
                    atomicAdd(&cols[c0 + 1], v1);
                }
            }
        }
        __syncthreads();
        if (tid < 128 && bsel < NB)
            atomicAdd(&ph[((size_t)(branch * NB + bsel)) * DDIM + n0 + tid], cols[tid]);
        __syncthreads();
    }
}

// ---------------- K6: layernorm + relu + last linear -----------------------
__global__ void final_kernel(const float* __restrict__ pooled,
                             const float* __restrict__ ln_g, const float* __restrict__ ln_b,
                             const float* __restrict__ W_last, const float* __restrict__ b_last,
                             float* __restrict__ out) {
    int row = blockIdx.y * NB + blockIdx.x;
    int tid = threadIdx.x;
    __shared__ float act[DDIM];
    __shared__ float red[128];

    float vals[8];
    float lsum = 0.f;
#pragma unroll
    for (int i = 0; i < 8; i++) {
        vals[i] = pooled[(size_t)row * DDIM + tid + i * 128];
        lsum += vals[i];
    }
    red[tid] = lsum;
    __syncthreads();
    for (int s = 64; s > 0; s >>= 1) {
        if (tid < s) red[tid] += red[tid + s];
        __syncthreads();
    }
    float mu = red[0] * (1.0f / DDIM);
    __syncthreads();
    float lsq = 0.f;
#pragma unroll
    for (int i = 0; i < 8; i++) {
        float d = vals[i] - mu;
        lsq += d * d;
    }
    red[tid] = lsq;
    __syncthreads();
    for (int s = 64; s > 0; s >>= 1) {
        if (tid < s) red[tid] += red[tid + s];
        __syncthreads();
    }
    float var = red[0] * (1.0f / DDIM);
    float vv = var + 1e-12f;
    float inv = rsqrtf(vv);
    inv = inv * (1.5f - 0.5f * vv * inv * inv);
    __syncthreads();
#pragma unroll
    for (int i = 0; i < 8; i++) {
        int d = tid + i * 128;
        float nvv = (vals[i] - mu) * inv * ln_g[d] + ln_b[d];
        act[d] = fmaxf(nvv, 0.f);
    }
    __syncthreads();
    if (tid < CDIM) {
        float accv = b_last[tid];
        for (int d = 0; d < DDIM; d++) accv += act[d] * W_last[(size_t)d * CDIM + tid];
        out[(size_t)row * CDIM + tid] = accv;
    }
}

// ---------------- launch ----------------------------------------------------
extern "C" void kernel_launch(void* const* d_in, const int* in_sizes, int n_in,
                              void* d_out, int out_size) {
    const float* x0 = (const float*)d_in[0];
    const float* x1 = (const float*)d_in[1];
    const float* x2 = (const float*)d_in[2];
    const int* m0 = (const int*)d_in[3];
    const int* m1 = (const int*)d_in[4];
    const int* m2 = (const int*)d_in[5];
    const float* W_attn = (const float*)d_in[6];
    const float* b_attn = (const float*)d_in[7];
    const float* W1 = (const float*)d_in[8];
    const float* b1 = (const float*)d_in[9];
    const float* W2 = (const float*)d_in[10];
    const float* b2 = (const float*)d_in[11];
    const float* ln_g = (const float*)d_in[12];
    const float* ln_b = (const float*)d_in[13];
    const float* W_last = (const float*)d_in[14];
    const float* b_last = (const float*)d_in[15];
    float* out = (float*)d_out;

    float *p_xsum, *p_nv, *p_u, *p_ub, *p_v, *p_attn, *p_ph, *p_pooled;
    float *p_xtf, *p_wtf;
    int *p_rank, *p_V, *p_off, *p_total, *p_batchof;
    cudaGetSymbolAddress((void**)&p_xsum, g_xsum);
    cudaGetSymbolAddress((void**)&p_nv, g_nv);
    cudaGetSymbolAddress((void**)&p_u, g_u);
    cudaGetSymbolAddress((void**)&p_ub, g_ub);
    cudaGetSymbolAddress((void**)&p_v, g_v);
    cudaGetSymbolAddress((void**)&p_attn, g_attn);
    cudaGetSymbolAddress((void**)&p_ph, g_ph);
    cudaGetSymbolAddress((void**)&p_pooled, g_pooled);
    cudaGetSymbolAddress((void**)&p_rank, g_rank);
    cudaGetSymbolAddress((void**)&p_V, g_V);
    cudaGetSymbolAddress((void**)&p_off, g_off);
    cudaGetSymbolAddress((void**)&p_total, g_total);
    cudaGetSymbolAddress((void**)&p_batchof, g_batchof);
    cudaGetSymbolAddress((void**)&p_xtf, g_xtf);
    cudaGetSymbolAddress((void**)&p_wtf, g_wtf);

    cudaFuncSetAttribute(big_mma_kernel, cudaFuncAttributeMaxDynamicSharedMemorySize,
                         SMEM_REQ);

    combo_kernel<<<1408, 256>>>(W1, p_wtf, p_ph, p_xsum, p_u, p_v,
                                p_pooled, p_ub, p_attn);
    mask_scan_kernel<<<dim3(NB, 3), 512>>>(m0, m1, m2, p_rank, p_V, p_nv);
    offsets_kernel<<<1, 96>>>(p_V, p_off, p_total, p_batchof);
    convsum_kernel<<<dim3(16, NB, 3), 256>>>(x0, x1, x2, p_rank, p_off,
                                             p_xtf, p_xsum, p_batchof);
    gemm96_kernel<0><<<dim3(16, 3, 8), 256>>>(p_xsum, W_attn, p_u, b_attn, p_nv, p_ub);
    gemm96_kernel<1><<<dim3(16, 3, 8), 256>>>(p_u, W_attn, p_v, nullptr, nullptr, nullptr);
    s_softmax_kernel<<<dim3(NB, 3), 512>>>(p_xtf, p_off, p_V, p_v, p_ub, p_attn);
    big_mma_kernel<<<dim3(8, 192), 512, SMEM_REQ>>>(p_xtf, p_wtf, b1, p_attn,
                                                    p_batchof, p_total, p_ph);
    gemm96_kernel<2><<<dim3(16, 3, 8), 256>>>(p_ph, W2, p_pooled, b2, nullptr, nullptr);
    final_kernel<<<dim3(NB, 3), 128>>>(p_pooled, ln_g, ln_b, W_last, b_last, out);
}

// round 16
// speedup vs baseline: 1.0853x; 1.0853x over previous
#include <cuda_runtime.h>
#include <cuda_bf16.h>
#include <cstdint>
#include <math.h>

// Problem constants
#define NB   32
#define TLEN 512
#define DDIM 1024
#define CDIM 120
#define NROWS 96
#define INV_SCALE 0.015625f // 1/64
#define TOTROWS 49152
#define BR_STRIDE 16384     // compact rows per branch (max 32*512)

#define NEG_INF __int_as_float(0xff800000)

// ---------------- scratch (device globals) ----------------------------------
__device__ float g_xsum[NROWS * DDIM];
__device__ float g_nv[NROWS];
__device__ float g_u[NROWS * DDIM];
__device__ float g_ub[NROWS];
__device__ float g_v[NROWS * DDIM];
__device__ float g_attn[3 * BR_STRIDE];   // compacted softmax weights
__device__ int   g_batchof[3 * BR_STRIDE];
__device__ float g_ph[NROWS * DDIM];
__device__ float g_pooled[NROWS * DDIM];
__device__ int   g_rank[NROWS * TLEN];    // local rank within batch, -1 masked
__device__ int   g_V[NROWS];              // valid count per batch-row
__device__ int   g_off[NROWS];            // exclusive offset of batch in branch
__device__ int   g_total[3];              // valid tokens per branch
// tf32 operands (globally compacted per branch; stored as fp32 bit patterns)
__device__ float g_xtf[(size_t)TOTROWS * DDIM];
__device__ float g_wtf[DDIM * DDIM];      // W1 transposed, tf32-rounded

// =================== helpers =================================================
__device__ __forceinline__ void cp16(void* d, const void* s) {
    asm volatile("cp.async.cg.shared.global [%0], [%1], 16;"
                 :: "l"(__cvta_generic_to_shared(d)), "l"(s));
}
__device__ __forceinline__ void cp_commit() {
    asm volatile("cp.async.commit_group;" ::: "memory");
}
__device__ __forceinline__ void cp_wait0() {
    asm volatile("cp.async.wait_group 0;" ::: "memory");
}
__device__ __forceinline__ void mma_tf32(float* d, const uint32_t* a, const uint32_t* b) {
    asm volatile(
        "mma.sync.aligned.m16n8k8.row.col.f32.tf32.tf32.f32 "
        "{%0,%1,%2,%3}, {%4,%5,%6,%7}, {%8,%9}, {%0,%1,%2,%3};"
        : "+f"(d[0]), "+f"(d[1]), "+f"(d[2]), "+f"(d[3])
        : "r"(a[0]), "r"(a[1]), "r"(a[2]), "r"(a[3]), "r"(b[0]), "r"(b[1]));
}
__device__ __forceinline__ void ldm4(uint32_t* r, uint32_t saddr) {
    asm volatile("ldmatrix.sync.aligned.m8n8.x4.shared.b16 {%0,%1,%2,%3}, [%4];"
                 : "=r"(r[0]), "=r"(r[1]), "=r"(r[2]), "=r"(r[3]) : "r"(saddr));
}
__device__ __forceinline__ float f2tf(float f) {
    uint32_t r;
    asm("cvt.rna.tf32.f32 %0, %1;" : "=r"(r) : "f"(f));
    return __uint_as_float(r);
}

// SMEM layout of big kernel: 2 stages x 36864B (M=128 x N=128 x K=32 tf32)
// row stride 144B (36 floats): ldmatrix row-starts hit disjoint bank quads.
#define ROW_B     144
#define APLANE    18432
#define STAGE_B   36864
#define OFF_ATT   73728   // 128 floats
#define OFF_BAT   74240   // 128 ints
#define OFF_B1    74752   // 128 floats
#define OFF_COL   75264   // 128 floats
#define SMEM_REQ  75776

// ---------------- K0: zero scratch + conv W1 -> tf32 transposed -------------
__global__ void combo_kernel(const float* __restrict__ W1,
                             float* __restrict__ wtf,
                             float* __restrict__ ph, float* __restrict__ xsum,
                             float* __restrict__ u, float* __restrict__ v,
                             float* __restrict__ pooled, float* __restrict__ ub,
                             float* __restrict__ attn) {
    int bx = blockIdx.x;
    if (bx < 384) {
        int i = bx * 256 + threadIdx.x;   // covers 98304
        ph[i] = 0.f; xsum[i] = 0.f; u[i] = 0.f; v[i] = 0.f; pooled[i] = 0.f;
        if (i < NROWS) ub[i] = 0.f;
        if (i < 3 * BR_STRIDE) attn[i] = 0.f;
    } else {
        __shared__ float tile[32][33];
        int b = bx - 384;
        int n0 = (b & 31) * 32, k0 = (b >> 5) * 32;
        int tx = threadIdx.x & 31, ty = threadIdx.x >> 5;
        for (int r = ty; r < 32; r += 8)
            tile[r][tx] = W1[(size_t)(k0 + r) * DDIM + n0 + tx];
        __syncthreads();
        for (int r = ty; r < 32; r += 8) {
            size_t o = (size_t)(n0 + r) * DDIM + k0 + tx;
            wtf[o] = f2tf(tile[tx][r]);   // = W1[k0+tx][n0+r]
        }
    }
}

// ---------------- K0b: mask scan via ballot/popcount -------------------------
__global__ void mask_scan_kernel(const int* __restrict__ m0, const int* __restrict__ m1,
                                 const int* __restrict__ m2,
                                 int* __restrict__ rank, int* __restrict__ V,
                                 float* __restrict__ nv) {
    int b = blockIdx.x, br = blockIdx.y;
    const int* M = ((br == 0) ? m0 : (br == 1) ? m1 : m2) + (size_t)b * TLEN;
    int row = br * NB + b;
    int tid = threadIdx.x;  // 512
    int lane = tid & 31, w = tid >> 5;
    __shared__ int wbase[16];
    int valid = (M[tid] == 0) ? 1 : 0;
    unsigned bal = __ballot_sync(0xffffffffu, valid);
    int pre = __popc(bal & ((1u << lane) - 1u));
    if (lane == 31) wbase[w] = pre + valid;
    __syncthreads();
    if (w == 0) {
        int v16 = (lane < 16) ? wbase[lane] : 0;
        int s = v16;
#pragma unroll
        for (int o = 1; o < 16; o <<= 1) {
            int t = __shfl_up_sync(0xffffffffu, s, o);
            if (lane >= o) s += t;
        }
        if (lane < 16) wbase[lane] = s - v16;   // exclusive
        if (lane == 15) { V[row] = s; nv[row] = (float)s; }
    }
    __syncthreads();
    rank[row * TLEN + tid] = valid ? (wbase[w] + pre) : -1;
}

// ---------------- K0c: offsets (warp scan) + pad fill of batchof -------------
__global__ void offsets_kernel(const int* __restrict__ V, int* __restrict__ off,
                               int* __restrict__ total, int* __restrict__ batchof) {
    int tid = threadIdx.x;   // 96
    if (tid >= 96) return;
    int br = tid >> 5, lane = tid & 31;
    int v = V[br * 32 + lane];
    int s = v;
#pragma unroll
    for (int o = 1; o < 32; o <<= 1) {
        int t = __shfl_up_sync(0xffffffffu, s, o);
        if (lane >= o) s += t;
    }
    off[br * 32 + lane] = s - v;
    int tot = __shfl_sync(0xffffffffu, s, 31);
    if (lane == 31) total[br] = tot;
    int up = (tot + 127) & ~127;      // pad to M=128 tile granularity
    for (int i = tot + lane; i < up; i += 32)
        batchof[br * BR_STRIDE + i] = NB - 1;
}

// ---------------- fused: valid x -> compacted tf32 plane + masked sum -------
// grid (16, 32, 3): 32-token chunks.
__global__ void convsum_kernel(const float* __restrict__ x0, const float* __restrict__ x1,
                               const float* __restrict__ x2,
                               const int* __restrict__ rank,
                               const int* __restrict__ off,
                               float* __restrict__ xtf,
                               float* __restrict__ xsum, int* __restrict__ batchof) {
    int ch = blockIdx.x, b = blockIdx.y, br = blockIdx.z;
    const float* X = (br == 0) ? x0 : (br == 1) ? x1 : x2;
    int row = br * NB + b;
    __shared__ int smr[32];
    __shared__ int soff;
    int tid = threadIdx.x;
    if (tid < 32) smr[tid] = rank[row * TLEN + ch * 32 + tid];
    if (tid == 0) soff = off[row];
    __syncthreads();
    size_t cbase = (size_t)br * BR_STRIDE + soff;
    if (tid < 32 && smr[tid] >= 0) batchof[cbase + smr[tid]] = b;

    const float* xp = X + ((size_t)b * TLEN + ch * 32) * DDIM + tid * 4;
    float ax = 0.f, ay = 0.f, az = 0.f, aw = 0.f;
#pragma unroll 1
    for (int t = 0; t < 32; t += 2) {
        int rk0 = smr[t], rk1 = smr[t + 1];
        float4 v0, v1;
        if (rk0 >= 0) v0 = *(const float4*)(xp + (size_t)t * DDIM);
        if (rk1 >= 0) v1 = *(const float4*)(xp + (size_t)(t + 1) * DDIM);
        if (rk0 >= 0) {
            float4 o4;
            o4.x = f2tf(v0.x); o4.y = f2tf(v0.y);
            o4.z = f2tf(v0.z); o4.w = f2tf(v0.w);
            *(float4*)(xtf + (cbase + rk0) * DDIM + tid * 4) = o4;
            ax += v0.x; ay += v0.y; az += v0.z; aw += v0.w;
        }
        if (rk1 >= 0) {
            float4 o4;
            o4.x = f2tf(v1.x); o4.y = f2tf(v1.y);
            o4.z = f2tf(v1.z); o4.w = f2tf(v1.w);
            *(float4*)(xtf + (cbase + rk1) * DDIM + tid * 4) = o4;
            ax += v1.x; ay += v1.y; az += v1.z; aw += v1.w;
        }
    }
    float* xr = xsum + (size_t)row * DDIM + tid * 4;
    atomicAdd(xr + 0, ax);
    atomicAdd(xr + 1, ay);
    atomicAdd(xr + 2, az);
    atomicAdd(xr + 3, aw);
}

// ---------------- small GEMM, K-split x8: (96 x 1024) @ (1024 x 1024) -------
template <int MODE>
__global__ void gemm96_kernel(const float* __restrict__ A, const float* __restrict__ B,
                              float* __restrict__ C, const float* __restrict__ bias,
                              const float* __restrict__ nv, float* __restrict__ ub) {
    const int BK = 32;
    __shared__ float As[32][BK + 1];
    __shared__ float Bs[BK][64 + 1];
    int m0 = blockIdx.y * 32;
    int n0 = blockIdx.x * 64;
    int ks = blockIdx.z * 128;
    int tid = threadIdx.x;
    int tx = tid & 15, ty = tid >> 4;
    int lane = tid & 31;

    float acc[2][4] = {{0.f, 0.f, 0.f, 0.f}, {0.f, 0.f, 0.f, 0.f}};

    for (int k0 = ks; k0 < ks + 128; k0 += BK) {
#pragma unroll
        for (int i = 0; i < 4; i++) {
            int l = tid + i * 256;
            int r = l >> 5, k = l & 31;
            As[r][k] = A[(size_t)(m0 + r) * DDIM + k0 + k];
        }
        if (MODE == 1) {
#pragma unroll
            for (int i = 0; i < 8; i++) {
                int l = tid + i * 256;
                int kk = l & 31, n = l >> 5;
                Bs[kk][n] = B[(size_t)(n0 + n) * DDIM + k0 + kk];
            }
        } else {
#pragma unroll
            for (int i = 0; i < 8; i++) {
                int l = tid + i * 256;
                int kk = l >> 6, n = l & 63;
                Bs[kk][n] = B[(size_t)(k0 + kk) * DDIM + n0 + n];
            }
        }
        __syncthreads();
#pragma unroll
        for (int kk = 0; kk < BK; kk++) {
            float a0 = As[ty * 2 + 0][kk];
            float a1 = As[ty * 2 + 1][kk];
#pragma unroll
            for (int j = 0; j < 4; j++) {
                float bv = Bs[kk][tx * 4 + j];
                acc[0][j] += a0 * bv;
                acc[1][j] += a1 * bv;
            }
        }
        __syncthreads();
    }

    float vv[2][4];
#pragma unroll
    for (int i = 0; i < 2; i++) {
        int r = m0 + ty * 2 + i;
#pragma unroll
        for (int j = 0; j < 4; j++) {
            int c = n0 + tx * 4 + j;
            float v = acc[i][j];
            if (MODE == 0 && blockIdx.z == 0) v += nv[r] * bias[c];
            if (MODE == 2 && blockIdx.z == 0) v += bias[c];
            vv[i][j] = v;
            atomicAdd(&C[(size_t)r * DDIM + c], v);
        }
    }
    if (MODE == 0) {
        float u0 = 0.f, u1 = 0.f;
#pragma unroll
        for (int j = 0; j < 4; j++) {
            float ba = bias[n0 + tx * 4 + j];
            u0 += vv[0][j] * ba;
            u1 += vv[1][j] * ba;
        }
#pragma unroll
        for (int o = 8; o > 0; o >>= 1) {
            u0 += __shfl_xor_sync(0xffffffffu, u0, o);
            u1 += __shfl_xor_sync(0xffffffffu, u1, o);
        }
        if ((lane & 15) == 0) {
            atomicAdd(&ub[m0 + ty * 2 + 0], u0);
            atomicAdd(&ub[m0 + ty * 2 + 1], u1);
        }
    }
}

// ---------------- K3+K4 fused: scores over compact tf32 plane + softmax -----
// grid (NB, 3), 1024 threads; warp = one token, strided by 32.
__global__ void s_softmax_kernel(const float* __restrict__ xtf,
                                 const int* __restrict__ off, const int* __restrict__ V,
                                 const float* __restrict__ v, const float* __restrict__ ub,
                                 float* __restrict__ attn) {
    int b = blockIdx.x, br = blockIdx.y;
    int row = br * NB + b;
    int base = off[row];
    int Vr = V[row];
    int tid = threadIdx.x;
    int w = tid >> 5, lane = tid & 31;
    __shared__ float sbuf[TLEN];
    __shared__ float red[1024];
    float ubr = ub[row];
    const float* vr = v + (size_t)row * DDIM;

    for (int t = w; t < Vr; t += 32) {
        size_t cr = (size_t)br * BR_STRIDE + base + t;
        const float* xr = xtf + cr * DDIM;
        float acc = 0.f;
#pragma unroll
        for (int i = 0; i < 8; i++) {
            int d = lane * 4 + i * 128;
            float4 xv = *(const float4*)&xr[d];
            float4 vv = *(const float4*)&vr[d];
            acc += xv.x * vv.x + xv.y * vv.y + xv.z * vv.z + xv.w * vv.w;
        }
#pragma unroll
        for (int o = 16; o > 0; o >>= 1) acc += __shfl_xor_sync(0xffffffffu, acc, o);
        if (lane == 0) sbuf[t] = (acc + ubr) * INV_SCALE;
    }
    __syncthreads();

    float v0 = (tid < Vr) ? sbuf[tid] : NEG_INF;
    red[tid] = v0;
    __syncthreads();
    for (int st = 512; st > 0; st >>= 1) {
        if (tid < st) red[tid] = fmaxf(red[tid], red[tid + st]);
        __syncthreads();
    }
    float mx = red[0];
    __syncthreads();
    float e0 = (tid < Vr) ? expf(v0 - mx) : 0.f;
    red[tid] = e0;
    __syncthreads();
    for (int st = 512; st > 0; st >>= 1) {
        if (tid < st) red[tid] += red[tid + st];
        __syncthreads();
    }
    float inv = 1.0f / red[0];
    if (tid < Vr) attn[(size_t)br * BR_STRIDE + base + tid] = e0 * inv;
}

// ---------------- K5: single-pass tf32 mma GEMM over compacted rows ---------
// grid (8, 384): bx = N-block; branch = by>>7, tile = by&127.
// m16n8k8 tf32; single-sync pipelined stages; segmented epilogue; occ 2.
__global__ __launch_bounds__(256, 2) void big_mma_kernel(
    const float* __restrict__ xtf, const float* __restrict__ wtf,
    const float* __restrict__ b1, const float* __restrict__ attn,
    const int* __restrict__ batchof, const int* __restrict__ total,
    float* __restrict__ ph) {
    extern __shared__ __align__(16) char smc[];
    float* att_s = (float*)(smc + OFF_ATT);
    int*   bat_s = (int*)(smc + OFF_BAT);
    float* b1s   = (float*)(smc + OFF_B1);
    float* cols  = (float*)(smc + OFF_COL);
    uint32_t sbase = (uint32_t)__cvta_generic_to_shared(smc);

    int by = blockIdx.y;
    int branch = by >> 7, tile = by & 127;
    if (tile * 128 >= total[branch]) return;

    int tid = threadIdx.x;
    int wid = tid >> 5, lane = tid & 31;
    int wm = wid >> 2, wn = wid & 3;
    int g = lane >> 2, tg = lane & 3;
    int n0 = blockIdx.x * 128;
    size_t rowbase = (size_t)branch * BR_STRIDE + tile * 128;

    auto load_stage = [&](int st) {
        char* buf = smc + (st & 1) * STAGE_B;
        int k0 = st * 32;
#pragma unroll
        for (int c = tid; c < 1024; c += 256) {
            int r = c >> 3, j = c & 7;
            int off = r * ROW_B + j * 16;
            cp16(buf + off, xtf + (rowbase + r) * DDIM + k0 + j * 4);
            cp16(buf + APLANE + off, wtf + (size_t)(n0 + r) * DDIM + k0 + j * 4);
        }
    };

    load_stage(0); cp_commit();

    if (tid < 128) {
        att_s[tid] = attn[rowbase + tid];
        bat_s[tid] = batchof[rowbase + tid];
        b1s[tid] = b1[n0 + tid];
    }

    float acc[4][4][4];
#pragma unroll
    for (int mi = 0; mi < 4; mi++)
#pragma unroll
        for (int ni = 0; ni < 4; ni++)
#pragma unroll
            for (int j = 0; j < 4; j++) acc[mi][ni][j] = 0.f;

    uint32_t a_l = (uint32_t)((wm * 64 + (lane & 15)) * ROW_B + (lane >> 4) * 16);
    uint32_t b_l = (uint32_t)((wn * 32 + (lane & 7) + ((lane >> 4) << 3)) * ROW_B +
                              ((lane >> 3) & 1) * 16);

    for (int st = 0; st < 32; ++st) {
        cp_wait0();
        __syncthreads();
        if (st + 1 < 32) { load_stage(st + 1); cp_commit(); }
        uint32_t buf = sbase + (uint32_t)(st & 1) * STAGE_B;
#pragma unroll
        for (int kb = 0; kb < 4; ++kb) {
            uint32_t aoff = buf + a_l + (uint32_t)kb * 32u;
            uint32_t boff = buf + APLANE + b_l + (uint32_t)kb * 32u;
            uint32_t a[4][4], b[2][4];
#pragma unroll
            for (int mi = 0; mi < 4; mi++) ldm4(a[mi], aoff + mi * (16 * ROW_B));
#pragma unroll
            for (int p = 0; p < 2; p++) ldm4(b[p], boff + p * (16 * ROW_B));
#pragma unroll
            for (int mi = 0; mi < 4; mi++)
#pragma unroll
                for (int ni = 0; ni < 4; ni++)
                    mma_tf32(acc[mi][ni], a[mi], &b[ni >> 1][(ni & 1) * 2]);
        }
    }

    // ---- epilogue: relu precompute, then per-segment weighted reduce --------
#pragma unroll
    for (int mi = 0; mi < 4; mi++)
#pragma unroll
        for (int ni = 0; ni < 4; ni++) {
            int c0 = wn * 32 + ni * 8 + tg * 2;
            float bv0 = b1s[c0], bv1 = b1s[c0 + 1];
            acc[mi][ni][0] = fmaxf(acc[mi][ni][0] + bv0, 0.f);
            acc[mi][ni][1] = fmaxf(acc[mi][ni][1] + bv1, 0.f);
            acc[mi][ni][2] = fmaxf(acc[mi][ni][2] + bv0, 0.f);
            acc[mi][ni][3] = fmaxf(acc[mi][ni][3] + bv1, 0.f);
        }
    int batch0 = bat_s[0];
    int nseg = bat_s[127] - batch0 + 1;
    for (int sg = 0; sg < nseg; ++sg) {
        int bsel = batch0 + sg;
        if (tid < 128) cols[tid] = 0.f;
        __syncthreads();
#pragma unroll
        for (int mi = 0; mi < 4; mi++) {
            int rA = wm * 64 + mi * 16 + g;
            float wA = (bat_s[rA] == bsel) ? att_s[rA] : 0.f;
            float wB = (bat_s[rA + 8] == bsel) ? att_s[rA + 8] : 0.f;
#pragma unroll
            for (int ni = 0; ni < 4; ni++) {
                int c0 = wn * 32 + ni * 8 + tg * 2;
                float v0 = acc[mi][ni][0] * wA + acc[mi][ni][2] * wB;
                float v1 = acc[mi][ni][1] * wA + acc[mi][ni][3] * wB;
#pragma unroll
                for (int o = 4; o <= 16; o <<= 1) {
                    v0 += __shfl_xor_sync(0xffffffffu, v0, o);
                    v1 += __shfl_xor_sync(0xffffffffu, v1, o);
                }
                if (g == 0) {
                    atomicAdd(&cols[c0], v0);
                    atomicAdd(&cols[c0 + 1], v1);
                }
            }
        }
        __syncthreads();
        if (tid < 128 && bsel < NB)
            atomicAdd(&ph[((size_t)(branch * NB + bsel)) * DDIM + n0 + tid], cols[tid]);
        __syncthreads();
    }
}

// ---------------- K6: layernorm + relu + last linear -----------------------
__global__ void final_kernel(const float* __restrict__ pooled,
                             const float* __restrict__ ln_g, const float* __restrict__ ln_b,
                             const float* __restrict__ W_last, const float* __restrict__ b_last,
                             float* __restrict__ out) {
    int row = blockIdx.y * NB + blockIdx.x;
    int tid = threadIdx.x;
    __shared__ float act[DDIM];
    __shared__ float red[128];

    float vals[8];
    float lsum = 0.f;
#pragma unroll
    for (int i = 0; i < 8; i++) {
        vals[i] = pooled[(size_t)row * DDIM + tid + i * 128];
        lsum += vals[i];
    }
    red[tid] = lsum;
    __syncthreads();
    for (int s = 64; s > 0; s >>= 1) {
        if (tid < s) red[tid] += red[tid + s];
        __syncthreads();
    }
    float mu = red[0] * (1.0f / DDIM);
    __syncthreads();
    float lsq = 0.f;
#pragma unroll
    for (int i = 0; i < 8; i++) {
        float d = vals[i] - mu;
        lsq += d * d;
    }
    red[tid] = lsq;
    __syncthreads();
    for (int s = 64; s > 0; s >>= 1) {
        if (tid < s) red[tid] += red[tid + s];
        __syncthreads();
    }
    float var = red[0] * (1.0f / DDIM);
    float vv = var + 1e-12f;
    float inv = rsqrtf(vv);
    inv = inv * (1.5f - 0.5f * vv * inv * inv);
    __syncthreads();
#pragma unroll
    for (int i = 0; i < 8; i++) {
        int d = tid + i * 128;
        float nvv = (vals[i] - mu) * inv * ln_g[d] + ln_b[d];
        act[d] = fmaxf(nvv, 0.f);
    }
    __syncthreads();
    if (tid < CDIM) {
        float accv = b_last[tid];
        for (int d = 0; d < DDIM; d++) accv += act[d] * W_last[(size_t)d * CDIM + tid];
        out[(size_t)row * CDIM + tid] = accv;
    }
}

// ---------------- launch ----------------------------------------------------
extern "C" void kernel_launch(void* const* d_in, const int* in_sizes, int n_in,
                              void* d_out, int out_size) {
    const float* x0 = (const float*)d_in[0];
    const float* x1 = (const float*)d_in[1];
    const float* x2 = (const float*)d_in[2];
    const int* m0 = (const int*)d_in[3];
    const int* m1 = (const int*)d_in[4];
    const int* m2 = (const int*)d_in[5];
    const float* W_attn = (const float*)d_in[6];
    const float* b_attn = (const float*)d_in[7];
    const float* W1 = (const float*)d_in[8];
    const float* b1 = (const float*)d_in[9];
    const float* W2 = (const float*)d_in[10];
    const float* b2 = (const float*)d_in[11];
    const float* ln_g = (const float*)d_in[12];
    const float* ln_b = (const float*)d_in[13];
    const float* W_last = (const float*)d_in[14];
    const float* b_last = (const float*)d_in[15];
    float* out = (float*)d_out;

    float *p_xsum, *p_nv, *p_u, *p_ub, *p_v, *p_attn, *p_ph, *p_pooled;
    float *p_xtf, *p_wtf;
    int *p_rank, *p_V, *p_off, *p_total, *p_batchof;
    cudaGetSymbolAddress((void**)&p_xsum, g_xsum);
    cudaGetSymbolAddress((void**)&p_nv, g_nv);
    cudaGetSymbolAddress((void**)&p_u, g_u);
    cudaGetSymbolAddress((void**)&p_ub, g_ub);
    cudaGetSymbolAddress((void**)&p_v, g_v);
    cudaGetSymbolAddress((void**)&p_attn, g_attn);
    cudaGetSymbolAddress((void**)&p_ph, g_ph);
    cudaGetSymbolAddress((void**)&p_pooled, g_pooled);
    cudaGetSymbolAddress((void**)&p_rank, g_rank);
    cudaGetSymbolAddress((void**)&p_V, g_V);
    cudaGetSymbolAddress((void**)&p_off, g_off);
    cudaGetSymbolAddress((void**)&p_total, g_total);
    cudaGetSymbolAddress((void**)&p_batchof, g_batchof);
    cudaGetSymbolAddress((void**)&p_xtf, g_xtf);
    cudaGetSymbolAddress((void**)&p_wtf, g_wtf);

    cudaFuncSetAttribute(big_mma_kernel, cudaFuncAttributeMaxDynamicSharedMemorySize,
                         SMEM_REQ);

    combo_kernel<<<1408, 256>>>(W1, p_wtf, p_ph, p_xsum, p_u, p_v,
                                p_pooled, p_ub, p_attn);
    mask_scan_kernel<<<dim3(NB, 3), 512>>>(m0, m1, m2, p_rank, p_V, p_nv);
    offsets_kernel<<<1, 96>>>(p_V, p_off, p_total, p_batchof);
    convsum_kernel<<<dim3(16, NB, 3), 256>>>(x0, x1, x2, p_rank, p_off,
                                             p_xtf, p_xsum, p_batchof);
    gemm96_kernel<0><<<dim3(16, 3, 8), 256>>>(p_xsum, W_attn, p_u, b_attn, p_nv, p_ub);
    gemm96_kernel<1><<<dim3(16, 3, 8), 256>>>(p_u, W_attn, p_v, nullptr, nullptr, nullptr);
    s_softmax_kernel<<<dim3(NB, 3), 1024>>>(p_xtf, p_off, p_V, p_v, p_ub, p_attn);
    big_mma_kernel<<<dim3(8, 384), 256, SMEM_REQ>>>(p_xtf, p_wtf, b1, p_attn,
                                                    p_batchof, p_total, p_ph);
    gemm96_kernel<2><<<dim3(16, 3, 8), 256>>>(p_ph, W2, p_pooled, b2, nullptr, nullptr);
    final_kernel<<<dim3(NB, 3), 128>>>(p_pooled, ln_g, ln_b, W_last, b_last, out);
}